// round 1
// baseline (speedup 1.0000x reference)
#include <cuda_runtime.h>
#include <cstdint>

#define BB 2
#define SS 2048
#define HH 1024
#define NH 16
#define HD 64
#define QKV_ELEMS (BB*NH*SS*HD)   // 4,194,304

// Scratch for projected q, k, v in [B, heads, S, hd] layout (16 MB each).
__device__ float g_q[QKV_ELEMS];
__device__ float g_k[QKV_ELEMS];
__device__ float g_v[QKV_ELEMS];

// ---------------------------------------------------------------------------
// Kernel 1: projection GEMM.  Y = X @ W^T + b, remapped to [B, heads, S, hd].
// X: [4096, 1024] row-major.  W: [1024, 1024] row-major (we need W^T so
// B-operand rows are W rows, K-contiguous).  BM=128, BN=128, BK=16,
// 256 threads, 8x8 microtile.
// ---------------------------------------------------------------------------
__global__ __launch_bounds__(256) void proj_kernel(
    const float* __restrict__ X, const float* __restrict__ W,
    const float* __restrict__ bias, float* __restrict__ Y)
{
    __shared__ float As[16][128];
    __shared__ float Bs[16][128];

    const int r0 = blockIdx.y * 128;
    const int c0 = blockIdx.x * 128;
    const int t  = threadIdx.x;
    const int tx = t & 15;
    const int ty = t >> 4;

    float acc[8][8];
#pragma unroll
    for (int i = 0; i < 8; i++)
#pragma unroll
        for (int j = 0; j < 8; j++) acc[i][j] = 0.0f;

    for (int k0 = 0; k0 < HH; k0 += 16) {
        // Load A tile (128x16) transposed into As[k][r]; 512 float4, 2/thread.
#pragma unroll
        for (int u = 0; u < 2; u++) {
            int l = u * 256 + t;
            int r = l >> 2;
            int kq = l & 3;
            float4 v = *(const float4*)(X + (size_t)(r0 + r) * HH + k0 + kq * 4);
            As[kq*4+0][r] = v.x; As[kq*4+1][r] = v.y;
            As[kq*4+2][r] = v.z; As[kq*4+3][r] = v.w;
        }
        // Load B tile: Bs[k][c] = W[c0+c][k0+k]
#pragma unroll
        for (int u = 0; u < 2; u++) {
            int l = u * 256 + t;
            int c = l >> 2;
            int kq = l & 3;
            float4 v = *(const float4*)(W + (size_t)(c0 + c) * HH + k0 + kq * 4);
            Bs[kq*4+0][c] = v.x; Bs[kq*4+1][c] = v.y;
            Bs[kq*4+2][c] = v.z; Bs[kq*4+3][c] = v.w;
        }
        __syncthreads();

#pragma unroll
        for (int kk = 0; kk < 16; kk++) {
            float a[8], b[8];
            *(float4*)&a[0] = *(float4*)&As[kk][ty*8];
            *(float4*)&a[4] = *(float4*)&As[kk][ty*8+4];
            *(float4*)&b[0] = *(float4*)&Bs[kk][tx*8];
            *(float4*)&b[4] = *(float4*)&Bs[kk][tx*8+4];
#pragma unroll
            for (int i = 0; i < 8; i++)
#pragma unroll
                for (int j = 0; j < 8; j++)
                    acc[i][j] += a[i] * b[j];
        }
        __syncthreads();
    }

    // Epilogue: add bias, remap row=(b,s), col=(h,d) -> [b,h,s,d].
    const int cbase = c0 + tx * 8;          // 8 cols, never crosses a head
    const int h  = cbase / HD;
    const int d0 = cbase % HD;
    float bs[8];
#pragma unroll
    for (int j = 0; j < 8; j++) bs[j] = bias[cbase + j];

#pragma unroll
    for (int i = 0; i < 8; i++) {
        int r = r0 + ty * 8 + i;
        int b = r / SS, s = r % SS;
        float* dst = Y + (((size_t)(b * NH + h) * SS + s) * HD + d0);
        float4 o0 = make_float4(acc[i][0]+bs[0], acc[i][1]+bs[1],
                                acc[i][2]+bs[2], acc[i][3]+bs[3]);
        float4 o1 = make_float4(acc[i][4]+bs[4], acc[i][5]+bs[5],
                                acc[i][6]+bs[6], acc[i][7]+bs[7]);
        *(float4*)dst = o0;
        *(float4*)(dst + 4) = o1;
    }
}

// ---------------------------------------------------------------------------
// Kernel 2: scores = q @ k^T / 8 with key-padding mask -> raw scores written
// into the w output region.  Per (b,h) slice, tile 128(i) x 128(j), K=64
// entirely in smem.  Tiles stored transposed [d][i] (stride 132, 16B aligned)
// for conflict-free float4 operand reads.  256 threads, 8x8 microtile.
// ---------------------------------------------------------------------------
#define SC_STRIDE 132
__global__ __launch_bounds__(256) void scores_kernel(
    const int* __restrict__ mask, float* __restrict__ wbuf)
{
    extern __shared__ float sm2[];
    float* QsT = sm2;                     // [64][132]
    float* KsT = sm2 + 64 * SC_STRIDE;    // [64][132]
    __shared__ int msk[128];

    const int j0 = blockIdx.x * 128;
    const int i0 = blockIdx.y * 128;
    const int z  = blockIdx.z;            // b*NH + h
    const int bidx = z / NH;
    const int t  = threadIdx.x;
    const int tx = t & 15;
    const int ty = t >> 4;

    const float* qbase = g_q + ((size_t)z * SS + i0) * HD;  // 128x64 contiguous
    const float* kbase = g_k + ((size_t)z * SS + j0) * HD;

#pragma unroll
    for (int u = 0; u < 8; u++) {
        int l = u * 256 + t;          // float4 id, 2048 total
        int i = l >> 4;               // row within tile
        int dq = l & 15;              // float4 within row
        float4 v = ((const float4*)qbase)[l];
        int d = dq * 4;
        QsT[(d+0)*SC_STRIDE + i] = v.x; QsT[(d+1)*SC_STRIDE + i] = v.y;
        QsT[(d+2)*SC_STRIDE + i] = v.z; QsT[(d+3)*SC_STRIDE + i] = v.w;
        float4 w = ((const float4*)kbase)[l];
        KsT[(d+0)*SC_STRIDE + i] = w.x; KsT[(d+1)*SC_STRIDE + i] = w.y;
        KsT[(d+2)*SC_STRIDE + i] = w.z; KsT[(d+3)*SC_STRIDE + i] = w.w;
    }
    if (t < 128) msk[t] = mask[(size_t)bidx * SS + j0 + t];
    __syncthreads();

    float acc[8][8];
#pragma unroll
    for (int i = 0; i < 8; i++)
#pragma unroll
        for (int j = 0; j < 8; j++) acc[i][j] = 0.0f;

#pragma unroll 8
    for (int d = 0; d < 64; d++) {
        float a[8], b[8];
        *(float4*)&a[0] = *(float4*)&QsT[d*SC_STRIDE + ty*8];
        *(float4*)&a[4] = *(float4*)&QsT[d*SC_STRIDE + ty*8+4];
        *(float4*)&b[0] = *(float4*)&KsT[d*SC_STRIDE + tx*8];
        *(float4*)&b[4] = *(float4*)&KsT[d*SC_STRIDE + tx*8+4];
#pragma unroll
        for (int i = 0; i < 8; i++)
#pragma unroll
            for (int j = 0; j < 8; j++)
                acc[i][j] += a[i] * b[j];
    }

    const float NEG_INF = __int_as_float(0xff800000);
#pragma unroll
    for (int ii = 0; ii < 8; ii++) {
        int row = i0 + ty * 8 + ii;
        float* dst = wbuf + ((size_t)z * SS + row) * SS + j0 + tx * 8;
        float vals[8];
#pragma unroll
        for (int jj = 0; jj < 8; jj++) {
            float s = acc[ii][jj] * 0.125f;
            vals[jj] = (msk[tx*8 + jj] > 0) ? NEG_INF : s;
        }
        *(float4*)dst       = *(float4*)&vals[0];
        *(float4*)(dst + 4) = *(float4*)&vals[4];
    }
}

// ---------------------------------------------------------------------------
// Kernel 3: per-row softmax + hard threshold + L1 renormalize, in place.
// One block (256 threads) per row of 2048; 8 elements/thread.
// Uses accurate expf and true IEEE division to match the fp32 reference
// as closely as possible (threshold flips are the dominant error source).
// ---------------------------------------------------------------------------
__device__ __forceinline__ float warpMax(float v) {
#pragma unroll
    for (int o = 16; o; o >>= 1) v = fmaxf(v, __shfl_xor_sync(0xffffffffu, v, o));
    return v;
}
__device__ __forceinline__ float warpSum(float v) {
#pragma unroll
    for (int o = 16; o; o >>= 1) v += __shfl_xor_sync(0xffffffffu, v, o);
    return v;
}
__device__ float blockMax(float v, float* red) {
    v = warpMax(v);
    int w = threadIdx.x >> 5, lane = threadIdx.x & 31;
    if (lane == 0) red[w] = v;
    __syncthreads();
    float r = (lane < 8) ? red[lane] : __int_as_float(0xff800000);
    if (w == 0) { r = warpMax(r); if (lane == 0) red[0] = r; }
    __syncthreads();
    float out = red[0];
    __syncthreads();
    return out;
}
__device__ float blockSum(float v, float* red) {
    v = warpSum(v);
    int w = threadIdx.x >> 5, lane = threadIdx.x & 31;
    if (lane == 0) red[w] = v;
    __syncthreads();
    float r = (lane < 8) ? red[lane] : 0.0f;
    if (w == 0) { r = warpSum(r); if (lane == 0) red[0] = r; }
    __syncthreads();
    float out = red[0];
    __syncthreads();
    return out;
}

__global__ __launch_bounds__(256) void softmax_kernel(float* __restrict__ wbuf)
{
    __shared__ float red[8];
    const size_t row = blockIdx.x;
    float* p = wbuf + row * SS;
    const int t = threadIdx.x;

    float4 x0 = ((const float4*)p)[t];
    float4 x1 = ((const float4*)p)[t + 256];
    float v[8] = {x0.x, x0.y, x0.z, x0.w, x1.x, x1.y, x1.z, x1.w};

    float m = v[0];
#pragma unroll
    for (int i = 1; i < 8; i++) m = fmaxf(m, v[i]);
    m = blockMax(m, red);

    float e[8], es = 0.0f;
#pragma unroll
    for (int i = 0; i < 8; i++) { e[i] = expf(v[i] - m); es += e[i]; }
    es = blockSum(es, red);

    float w[8], l1 = 0.0f;
#pragma unroll
    for (int i = 0; i < 8; i++) {
        float wi = e[i] / es;                    // IEEE fp32 divide
        wi = (wi < 0.001f) ? 0.0f : wi;          // hard threshold
        w[i] = wi;
        l1 += wi;
    }
    l1 = blockSum(l1, red);
    float denom = fmaxf(l1, 1e-12f);

#pragma unroll
    for (int i = 0; i < 8; i++) w[i] = w[i] / denom;

    float4 o0 = make_float4(w[0], w[1], w[2], w[3]);
    float4 o1 = make_float4(w[4], w[5], w[6], w[7]);
    ((float4*)p)[t]       = o0;
    ((float4*)p)[t + 256] = o1;
}

// ---------------------------------------------------------------------------
// Kernel 4: out = w @ v per (b,h) slice, with layout transform to [B,S,H].
// BM=128 (i), BN=64 (full hd), BK=32 (j).  256 threads, 8x4 microtile.
// ---------------------------------------------------------------------------
#define AV_STRIDE 132
__global__ __launch_bounds__(256) void av_kernel(
    const float* __restrict__ wbuf, float* __restrict__ out)
{
    __shared__ float WsT[32 * AV_STRIDE];   // [j][i]
    __shared__ float Vs[32 * 64];           // [j][d]

    const int i0 = blockIdx.x * 128;
    const int z  = blockIdx.y;              // b*NH + h
    const int bidx = z / NH;
    const int h    = z % NH;
    const int t  = threadIdx.x;
    const int tx = t & 15;
    const int ty = t >> 4;

    float acc[8][4];
#pragma unroll
    for (int i = 0; i < 8; i++)
#pragma unroll
        for (int j = 0; j < 4; j++) acc[i][j] = 0.0f;

    for (int j0 = 0; j0 < SS; j0 += 32) {
        // w tile 128x32 transposed
#pragma unroll
        for (int u = 0; u < 4; u++) {
            int l = u * 256 + t;      // float4 id, 1024 total
            int r = l >> 3;
            int jq = l & 7;
            float4 v = *(const float4*)(wbuf + ((size_t)z * SS + i0 + r) * SS + j0 + jq * 4);
            WsT[(jq*4+0)*AV_STRIDE + r] = v.x;
            WsT[(jq*4+1)*AV_STRIDE + r] = v.y;
            WsT[(jq*4+2)*AV_STRIDE + r] = v.z;
            WsT[(jq*4+3)*AV_STRIDE + r] = v.w;
        }
        // v tile 32x64, contiguous copy
        const float4* vsrc = (const float4*)(g_v + ((size_t)z * SS + j0) * HD);
#pragma unroll
        for (int u = 0; u < 2; u++) {
            int l = u * 256 + t;      // 512 float4
            ((float4*)Vs)[l] = vsrc[l];
        }
        __syncthreads();

#pragma unroll 8
        for (int j = 0; j < 32; j++) {
            float a[8], b[4];
            *(float4*)&a[0] = *(float4*)&WsT[j*AV_STRIDE + ty*8];
            *(float4*)&a[4] = *(float4*)&WsT[j*AV_STRIDE + ty*8+4];
            *(float4*)&b[0] = *(float4*)&Vs[j*64 + tx*4];
#pragma unroll
            for (int i = 0; i < 8; i++)
#pragma unroll
                for (int jj = 0; jj < 4; jj++)
                    acc[i][jj] += a[i] * b[jj];
        }
        __syncthreads();
    }

#pragma unroll
    for (int ii = 0; ii < 8; ii++) {
        int srow = i0 + ty * 8 + ii;
        float* dst = out + ((size_t)bidx * SS + srow) * HH + h * HD + tx * 4;
        *(float4*)dst = make_float4(acc[ii][0], acc[ii][1], acc[ii][2], acc[ii][3]);
    }
}

// ---------------------------------------------------------------------------
extern "C" void kernel_launch(void* const* d_in, const int* in_sizes, int n_in,
                              void* d_out, int out_size)
{
    const float* query = (const float*)d_in[0];
    const float* key   = (const float*)d_in[1];
    const float* value = (const float*)d_in[2];
    const int*   mask  = (const int*)  d_in[3];
    const float* Wq    = (const float*)d_in[4];
    const float* bq    = (const float*)d_in[5];
    const float* Wk    = (const float*)d_in[6];
    const float* bk    = (const float*)d_in[7];
    const float* Wv    = (const float*)d_in[8];
    const float* bv    = (const float*)d_in[9];

    float* out  = (float*)d_out;
    float* wbuf = out + (size_t)BB * SS * HH;   // w output region

    float *qp, *kp, *vp;
    cudaGetSymbolAddress((void**)&qp, g_q);
    cudaGetSymbolAddress((void**)&kp, g_k);
    cudaGetSymbolAddress((void**)&vp, g_v);

    // 1) Projections
    dim3 gProj(HH / 128, (BB * SS) / 128);   // (8, 32)
    proj_kernel<<<gProj, 256>>>(query, Wq, bq, qp);
    proj_kernel<<<gProj, 256>>>(key,   Wk, bk, kp);
    proj_kernel<<<gProj, 256>>>(value, Wv, bv, vp);

    // 2) Scores (raw, masked) into w region
    size_t smScores = 2 * 64 * SC_STRIDE * sizeof(float);  // ~67.6 KB
    cudaFuncSetAttribute(scores_kernel,
                         cudaFuncAttributeMaxDynamicSharedMemorySize,
                         (int)smScores);
    dim3 gScores(SS / 128, SS / 128, BB * NH);   // (16, 16, 32)
    scores_kernel<<<gScores, 256, smScores>>>(mask, wbuf);

    // 3) Softmax + threshold + L1 renorm, in place
    softmax_kernel<<<BB * NH * SS, 256>>>(wbuf);

    // 4) out = w @ v
    dim3 gAV(SS / 128, BB * NH);   // (16, 32)
    av_kernel<<<gAV, 256>>>(wbuf, out);
}